// round 1
// baseline (speedup 1.0000x reference)
#include <cuda_runtime.h>

// Problem constants (fixed shapes)
// x: (32, 256, 56, 56) fp32
// out: (32, 256, 56, 56) fp32
#define BATCH 32
#define CH    256      // in channels == out filters
#define HW    3136     // 56*56
#define KTAPS 9

// ---------------- scratch (device globals; no runtime allocation) ----------
__device__ float g_maxi[BATCH * CH * 25];        // 5x5 max-pool bins
__device__ float g_wgt1[BATCH * CH * 9];         // relu(dw3x3(avg)+b1), 3x3
__device__ float g_W   [(size_t)BATCH * CH * CH * 9];  // [b][f][q][tap]  (75.5 MB)

__constant__ int c_bin_start[5] = {0, 11, 22, 33, 44};
__constant__ int c_bin_end[5]   = {12, 23, 34, 45, 56};

// ============================================================================
// Kernel 1: per-(b,c) adaptive avg+max pool 56x56 -> 5x5, fused depthwise
// 3x3 conv + bias + relu on the avg bins (valid, 5x5 -> 3x3).
// grid = 8192 blocks (b*256+c), 128 threads.
// ============================================================================
__global__ __launch_bounds__(128) void pool_kernel(
    const float* __restrict__ x,
    const float* __restrict__ w1,
    const float* __restrict__ b1)
{
    __shared__ float img[HW];
    __shared__ float avgb[25];

    int bc = blockIdx.x;              // b*256 + c
    int c  = bc & 255;
    int t  = threadIdx.x;

    // vectorized coalesced load of the whole 56x56 image (3136 floats)
    const float4* src4 = (const float4*)(x + (size_t)bc * HW);
    float4* img4 = (float4*)img;
    for (int i = t; i < HW / 4; i += 128) img4[i] = src4[i];
    __syncthreads();

    if (t < 25) {
        int bi = t / 5, bj = t % 5;
        int r0 = c_bin_start[bi], r1 = c_bin_end[bi];
        int c0 = c_bin_start[bj], c1 = c_bin_end[bj];
        float s = 0.f, m = -3.402823466e38f;
        for (int r = r0; r < r1; r++) {
            const float* row = img + r * 56;
            for (int cc = c0; cc < c1; cc++) {
                float v = row[cc];
                s += v;
                m = fmaxf(m, v);
            }
        }
        avgb[t] = s * (1.f / 144.f);          // all bins are 12x12
        g_maxi[bc * 25 + t] = m;
    }
    __syncthreads();

    if (t < 9) {
        int u = t / 3, v = t % 3;
        float acc = b1[c];
        #pragma unroll
        for (int i = 0; i < 3; i++)
            #pragma unroll
            for (int j = 0; j < 3; j++)
                acc += avgb[(u + i) * 5 + (v + j)] * w1[c * 9 + i * 3 + j];
        g_wgt1[bc * 9 + t] = fmaxf(acc, 0.f);
    }
}

// ============================================================================
// Kernel 2: dynamic-weight generation.
//   W[b][p][q][tap] = (wgt1[b,p,tap]*w2[p*256+q] + b2[p*256+q])
//                   * sigmoid( conv3x3(maxi[b,p], w_att[p*256+q]) + b_att[..] )
// grid = (256 p, 32 b), 256 threads (q). Writes 9 contiguous floats/thread.
// ============================================================================
__global__ __launch_bounds__(256) void gen_kernel(
    const float* __restrict__ w2,
    const float* __restrict__ b2,
    const float* __restrict__ w_att,
    const float* __restrict__ b_att)
{
    int p = blockIdx.x;
    int b = blockIdx.y;
    int q = threadIdx.x;
    int bp = b * CH + p;

    __shared__ float maxi_s[25];
    __shared__ float wgt1_s[9];
    if (q < 25) maxi_s[q] = g_maxi[bp * 25 + q];
    if (q >= 32 && q < 41) wgt1_s[q - 32] = g_wgt1[bp * 9 + (q - 32)];
    __syncthreads();

    int cidx = p * CH + q;
    float wa[9];
    #pragma unroll
    for (int k = 0; k < 9; k++) wa[k] = w_att[cidx * 9 + k];
    float w2c = w2[cidx], b2c = b2[cidx], bac = b_att[cidx];

    float* outp = g_W + (size_t)bp * CH * 9 + q * 9;
    #pragma unroll
    for (int u = 0; u < 3; u++)
        #pragma unroll
        for (int v = 0; v < 3; v++) {
            float s = bac;
            #pragma unroll
            for (int i = 0; i < 3; i++)
                #pragma unroll
                for (int j = 0; j < 3; j++)
                    s += maxi_s[(u + i) * 5 + (v + j)] * wa[i * 3 + j];
            float att = 1.f / (1.f + __expf(-s));
            outp[u * 3 + v] = (wgt1_s[u * 3 + v] * w2c + b2c) * att;
        }
}

// ============================================================================
// Kernel 3: per-sample dynamic 3x3 conv (pad 1, stride 1).
//   out[b,f,y,x] = sum_{q,i,j} x[b,q,y-1+i,x-1+j] * W[b][f][q][i*3+j]
// Implicit-GEMM tiling: block = (batch b, 128 filters, 2 output rows x 56 cols)
// 256 threads; each thread: 8 filters x 7 cols in registers (56 accums).
// c loop in chunks of 8 staged through shared memory.
// ============================================================================
#define TFILT 128
#define TROWS 2
#define CCHUNK 8
#define XS_ROWS 4            // TROWS + 2 halo
#define XS_COLS 58           // 56 + 2 halo
#define WS_LD   129          // 128 filters + 1 pad (conflict-free)

__global__ __launch_bounds__(256, 2) void conv_kernel(
    const float* __restrict__ x,
    float* __restrict__ out)
{
    __shared__ float xs[CCHUNK * XS_ROWS * XS_COLS];   // [c][row][col]
    __shared__ float ws[CCHUNK * 9 * WS_LD];           // [c*9+tap][f]

    int rowBase = blockIdx.x * TROWS;
    int fBase   = blockIdx.y * TFILT;
    int b       = blockIdx.z;
    int t  = threadIdx.x;
    int ty = t >> 4;          // 0..15 -> filters ty*8 .. ty*8+7
    int tx = t & 15;
    int rr = tx >> 3;         // 0..1  output row within tile
    int cc = tx & 7;          // cols cc + 8k, k = 0..6

    float acc[8][7];
    #pragma unroll
    for (int i = 0; i < 8; i++)
        #pragma unroll
        for (int k = 0; k < 7; k++) acc[i][k] = 0.f;

    const float* xb = x + (size_t)b * CH * HW;
    const float* wb = g_W + (size_t)(b * CH + fBase) * (CH * 9);

    for (int cb = 0; cb < CH; cb += CCHUNK) {
        // ---- stage x tile: 8 ch x 4 rows x 58 cols (halo, zero padded) ----
        for (int idx = t; idx < CCHUNK * XS_ROWS * XS_COLS; idx += 256) {
            int c_  = idx / (XS_ROWS * XS_COLS);
            int rem = idx - c_ * (XS_ROWS * XS_COLS);
            int row = rem / XS_COLS;
            int col = rem - row * XS_COLS;
            int gr = rowBase - 1 + row;
            int gc = col - 1;
            float v = 0.f;
            if ((unsigned)gr < 56u && (unsigned)gc < 56u)
                v = xb[(cb + c_) * HW + gr * 56 + gc];
            xs[idx] = v;
        }
        // ---- stage W tile: 128 f x (8 c x 9 taps), transposed to [r][f] ----
        for (int idx = t; idx < TFILT * CCHUNK * 9; idx += 256) {
            int f_ = idx / (CCHUNK * 9);
            int r  = idx - f_ * (CCHUNK * 9);
            ws[r * WS_LD + f_] = wb[f_ * (CH * 9) + cb * 9 + r];
        }
        __syncthreads();

        #pragma unroll 1
        for (int c_ = 0; c_ < CCHUNK; c_++) {
            #pragma unroll
            for (int tap = 0; tap < 9; tap++) {
                int i = tap / 3, j = tap % 3;
                const float* xrow = &xs[(c_ * XS_ROWS + rr + i) * XS_COLS + cc + j];
                float xv[7];
                #pragma unroll
                for (int k = 0; k < 7; k++) xv[k] = xrow[8 * k];
                const float* wrow = &ws[(c_ * 9 + tap) * WS_LD + ty * 8];
                float wv[8];
                #pragma unroll
                for (int ii = 0; ii < 8; ii++) wv[ii] = wrow[ii];
                #pragma unroll
                for (int ii = 0; ii < 8; ii++)
                    #pragma unroll
                    for (int k = 0; k < 7; k++)
                        acc[ii][k] = fmaf(wv[ii], xv[k], acc[ii][k]);
            }
        }
        __syncthreads();
    }

    // ---- write 8 filters x 7 cols ----
    float* ob = out + (size_t)(b * CH + fBase) * HW + (rowBase + rr) * 56;
    #pragma unroll
    for (int ii = 0; ii < 8; ii++) {
        float* orow = ob + (ty * 8 + ii) * HW;
        #pragma unroll
        for (int k = 0; k < 7; k++)
            orow[cc + 8 * k] = acc[ii][k];
    }
}

// ============================================================================
// launch
// inputs (metadata order): x, w1, b1, w2, b2, w_att, b_att
// ============================================================================
extern "C" void kernel_launch(void* const* d_in, const int* in_sizes, int n_in,
                              void* d_out, int out_size)
{
    const float* x     = (const float*)d_in[0];
    const float* w1    = (const float*)d_in[1];
    const float* b1    = (const float*)d_in[2];
    const float* w2    = (const float*)d_in[3];
    const float* b2    = (const float*)d_in[4];
    const float* w_att = (const float*)d_in[5];
    const float* b_att = (const float*)d_in[6];
    float* out = (float*)d_out;

    pool_kernel<<<BATCH * CH, 128>>>(x, w1, b1);

    dim3 ggrid(CH, BATCH);
    gen_kernel<<<ggrid, 256>>>(w2, b2, w_att, b_att);

    dim3 cgrid(56 / TROWS, CH / TFILT, BATCH);   // 28 x 2 x 32
    conv_kernel<<<cgrid, 256>>>(x, out);
}

// round 2
// speedup vs baseline: 1.5787x; 1.5787x over previous
#include <cuda_runtime.h>

// Problem constants (fixed shapes)
// x: (32, 256, 56, 56) fp32
// out: (32, 256, 56, 56) fp32
#define BATCH 32
#define CH    256      // in channels == out filters
#define HW    3136     // 56*56
#define KTAPS 9

// ---------------- scratch (device globals; no runtime allocation) ----------
__device__ float g_maxi[BATCH * CH * 25];        // 5x5 max-pool bins
__device__ float g_wgt1[BATCH * CH * 9];         // relu(dw3x3(avg)+b1), 3x3
__device__ float g_W   [(size_t)BATCH * CH * CH * 9];  // [b][f][q][tap]  (75.5 MB)

__constant__ int c_bin_start[5] = {0, 11, 22, 33, 44};
__constant__ int c_bin_end[5]   = {12, 23, 34, 45, 56};

// ============================================================================
// Kernel 1: per-(b,c) adaptive avg+max pool 56x56 -> 5x5, fused depthwise
// 3x3 conv + bias + relu on the avg bins (valid, 5x5 -> 3x3).
// grid = 8192 blocks (b*256+c), 128 threads.
// ============================================================================
__global__ __launch_bounds__(128) void pool_kernel(
    const float* __restrict__ x,
    const float* __restrict__ w1,
    const float* __restrict__ b1)
{
    __shared__ float img[HW];
    __shared__ float avgb[25];

    int bc = blockIdx.x;              // b*256 + c
    int c  = bc & 255;
    int t  = threadIdx.x;

    // vectorized coalesced load of the whole 56x56 image (3136 floats)
    const float4* src4 = (const float4*)(x + (size_t)bc * HW);
    float4* img4 = (float4*)img;
    for (int i = t; i < HW / 4; i += 128) img4[i] = src4[i];
    __syncthreads();

    if (t < 25) {
        int bi = t / 5, bj = t % 5;
        int r0 = c_bin_start[bi], r1 = c_bin_end[bi];
        int c0 = c_bin_start[bj], c1 = c_bin_end[bj];
        float s = 0.f, m = -3.402823466e38f;
        for (int r = r0; r < r1; r++) {
            const float* row = img + r * 56;
            for (int cc = c0; cc < c1; cc++) {
                float v = row[cc];
                s += v;
                m = fmaxf(m, v);
            }
        }
        avgb[t] = s * (1.f / 144.f);          // all bins are 12x12
        g_maxi[bc * 25 + t] = m;
    }
    __syncthreads();

    if (t < 9) {
        int u = t / 3, v = t % 3;
        float acc = b1[c];
        #pragma unroll
        for (int i = 0; i < 3; i++)
            #pragma unroll
            for (int j = 0; j < 3; j++)
                acc += avgb[(u + i) * 5 + (v + j)] * w1[c * 9 + i * 3 + j];
        g_wgt1[bc * 9 + t] = fmaxf(acc, 0.f);
    }
}

// ============================================================================
// Kernel 2: dynamic-weight generation.
//   W[b][p][q][tap] = (wgt1[b,p,tap]*w2[p*256+q] + b2[p*256+q])
//                   * sigmoid( conv3x3(maxi[b,p], w_att[p*256+q]) + b_att[..] )
// grid = (256 p, 32 b), 256 threads (q). Writes 9 contiguous floats/thread.
// ============================================================================
__global__ __launch_bounds__(256) void gen_kernel(
    const float* __restrict__ w2,
    const float* __restrict__ b2,
    const float* __restrict__ w_att,
    const float* __restrict__ b_att)
{
    int p = blockIdx.x;
    int b = blockIdx.y;
    int q = threadIdx.x;
    int bp = b * CH + p;

    __shared__ float maxi_s[25];
    __shared__ float wgt1_s[9];
    if (q < 25) maxi_s[q] = g_maxi[bp * 25 + q];
    if (q >= 32 && q < 41) wgt1_s[q - 32] = g_wgt1[bp * 9 + (q - 32)];
    __syncthreads();

    int cidx = p * CH + q;
    float wa[9];
    #pragma unroll
    for (int k = 0; k < 9; k++) wa[k] = w_att[cidx * 9 + k];
    float w2c = w2[cidx], b2c = b2[cidx], bac = b_att[cidx];

    float* outp = g_W + (size_t)bp * CH * 9 + q * 9;
    #pragma unroll
    for (int u = 0; u < 3; u++)
        #pragma unroll
        for (int v = 0; v < 3; v++) {
            float s = bac;
            #pragma unroll
            for (int i = 0; i < 3; i++)
                #pragma unroll
                for (int j = 0; j < 3; j++)
                    s += maxi_s[(u + i) * 5 + (v + j)] * wa[i * 3 + j];
            float att = 1.f / (1.f + __expf(-s));
            outp[u * 3 + v] = (wgt1_s[u * 3 + v] * w2c + b2c) * att;
        }
}

// ============================================================================
// Kernel 3: per-sample dynamic 3x3 conv (pad 1, stride 1).
//   out[b,f,y,x] = sum_{q,i,j} x[b,q,y-1+i,x-1+j] * W[b][f][q][i*3+j]
// Implicit-GEMM tiling: block = (batch b, 128 filters, 2 output rows x 56 cols)
// 256 threads; each thread: 8 filters x 7 cols in registers (56 accums).
// c loop in chunks of 8 staged through shared memory.
// ============================================================================
#define TFILT 128
#define TROWS 2
#define CCHUNK 8
#define XS_ROWS 4            // TROWS + 2 halo
#define XS_COLS 58           // 56 + 2 halo
#define WS_LD   129          // 128 filters + 1 pad (conflict-free)

__global__ __launch_bounds__(256, 2) void conv_kernel(
    const float* __restrict__ x,
    float* __restrict__ out)
{
    __shared__ float xs[CCHUNK * XS_ROWS * XS_COLS];   // [c][row][col]
    __shared__ float ws[CCHUNK * 9 * WS_LD];           // [c*9+tap][f]

    int rowBase = blockIdx.x * TROWS;
    int fBase   = blockIdx.y * TFILT;
    int b       = blockIdx.z;
    int t  = threadIdx.x;
    int ty = t >> 4;          // 0..15 -> filters ty*8 .. ty*8+7
    int tx = t & 15;
    int rr = tx >> 3;         // 0..1  output row within tile
    int cc = tx & 7;          // cols cc + 8k, k = 0..6

    float acc[8][7];
    #pragma unroll
    for (int i = 0; i < 8; i++)
        #pragma unroll
        for (int k = 0; k < 7; k++) acc[i][k] = 0.f;

    const float* xb = x + (size_t)b * CH * HW;
    const float* wb = g_W + (size_t)(b * CH + fBase) * (CH * 9);

    for (int cb = 0; cb < CH; cb += CCHUNK) {
        // ---- stage x tile: 8 ch x 4 rows x 58 cols (halo, zero padded) ----
        for (int idx = t; idx < CCHUNK * XS_ROWS * XS_COLS; idx += 256) {
            int c_  = idx / (XS_ROWS * XS_COLS);
            int rem = idx - c_ * (XS_ROWS * XS_COLS);
            int row = rem / XS_COLS;
            int col = rem - row * XS_COLS;
            int gr = rowBase - 1 + row;
            int gc = col - 1;
            float v = 0.f;
            if ((unsigned)gr < 56u && (unsigned)gc < 56u)
                v = xb[(cb + c_) * HW + gr * 56 + gc];
            xs[idx] = v;
        }
        // ---- stage W tile: 128 f x (8 c x 9 taps), transposed to [r][f] ----
        for (int idx = t; idx < TFILT * CCHUNK * 9; idx += 256) {
            int f_ = idx / (CCHUNK * 9);
            int r  = idx - f_ * (CCHUNK * 9);
            ws[r * WS_LD + f_] = wb[f_ * (CH * 9) + cb * 9 + r];
        }
        __syncthreads();

        #pragma unroll 1
        for (int c_ = 0; c_ < CCHUNK; c_++) {
            #pragma unroll
            for (int tap = 0; tap < 9; tap++) {
                int i = tap / 3, j = tap % 3;
                const float* xrow = &xs[(c_ * XS_ROWS + rr + i) * XS_COLS + cc + j];
                float xv[7];
                #pragma unroll
                for (int k = 0; k < 7; k++) xv[k] = xrow[8 * k];
                const float* wrow = &ws[(c_ * 9 + tap) * WS_LD + ty * 8];
                float wv[8];
                #pragma unroll
                for (int ii = 0; ii < 8; ii++) wv[ii] = wrow[ii];
                #pragma unroll
                for (int ii = 0; ii < 8; ii++)
                    #pragma unroll
                    for (int k = 0; k < 7; k++)
                        acc[ii][k] = fmaf(wv[ii], xv[k], acc[ii][k]);
            }
        }
        __syncthreads();
    }

    // ---- write 8 filters x 7 cols ----
    float* ob = out + (size_t)(b * CH + fBase) * HW + (rowBase + rr) * 56;
    #pragma unroll
    for (int ii = 0; ii < 8; ii++) {
        float* orow = ob + (ty * 8 + ii) * HW;
        #pragma unroll
        for (int k = 0; k < 7; k++)
            orow[cc + 8 * k] = acc[ii][k];
    }
}

// ============================================================================
// launch
// inputs (metadata order): x, w1, b1, w2, b2, w_att, b_att
// ============================================================================
extern "C" void kernel_launch(void* const* d_in, const int* in_sizes, int n_in,
                              void* d_out, int out_size)
{
    const float* x     = (const float*)d_in[0];
    const float* w1    = (const float*)d_in[1];
    const float* b1    = (const float*)d_in[2];
    const float* w2    = (const float*)d_in[3];
    const float* b2    = (const float*)d_in[4];
    const float* w_att = (const float*)d_in[5];
    const float* b_att = (const float*)d_in[6];
    float* out = (float*)d_out;

    pool_kernel<<<BATCH * CH, 128>>>(x, w1, b1);

    dim3 ggrid(CH, BATCH);
    gen_kernel<<<ggrid, 256>>>(w2, b2, w_att, b_att);

    dim3 cgrid(56 / TROWS, CH / TFILT, BATCH);   // 28 x 2 x 32
    conv_kernel<<<cgrid, 256>>>(x, out);
}

// round 3
// speedup vs baseline: 1.5874x; 1.0055x over previous
#include <cuda_runtime.h>

// Problem constants (fixed shapes)
// x: (32, 256, 56, 56) fp32
// out: (32, 256, 56, 56) fp32
#define BATCH 32
#define CH    256      // in channels == out filters
#define HW    3136     // 56*56
#define KTAPS 9

// ---------------- scratch (device globals; no runtime allocation) ----------
__device__ float g_maxi[BATCH * CH * 25];        // 5x5 max-pool bins
__device__ float g_wgt1[BATCH * CH * 9];         // relu(dw3x3(avg)+b1), 3x3
__device__ float g_W   [(size_t)BATCH * CH * CH * 9];  // [b][f][q][tap]  (75.5 MB)

__constant__ int c_bin_start[5] = {0, 11, 22, 33, 44};
__constant__ int c_bin_end[5]   = {12, 23, 34, 45, 56};

// ============================================================================
// Kernel 1: per-(b,c) adaptive avg+max pool 56x56 -> 5x5, fused depthwise
// 3x3 conv + bias + relu on the avg bins (valid, 5x5 -> 3x3).
// grid = 8192 blocks (b*256+c), 128 threads.
// ============================================================================
__global__ __launch_bounds__(128) void pool_kernel(
    const float* __restrict__ x,
    const float* __restrict__ w1,
    const float* __restrict__ b1)
{
    __shared__ float img[HW];
    __shared__ float avgb[25];

    int bc = blockIdx.x;              // b*256 + c
    int c  = bc & 255;
    int t  = threadIdx.x;

    // vectorized coalesced load of the whole 56x56 image (3136 floats)
    const float4* src4 = (const float4*)(x + (size_t)bc * HW);
    float4* img4 = (float4*)img;
    for (int i = t; i < HW / 4; i += 128) img4[i] = src4[i];
    __syncthreads();

    if (t < 25) {
        int bi = t / 5, bj = t % 5;
        int r0 = c_bin_start[bi], r1 = c_bin_end[bi];
        int c0 = c_bin_start[bj], c1 = c_bin_end[bj];
        float s = 0.f, m = -3.402823466e38f;
        for (int r = r0; r < r1; r++) {
            const float* row = img + r * 56;
            for (int cc = c0; cc < c1; cc++) {
                float v = row[cc];
                s += v;
                m = fmaxf(m, v);
            }
        }
        avgb[t] = s * (1.f / 144.f);          // all bins are 12x12
        g_maxi[bc * 25 + t] = m;
    }
    __syncthreads();

    if (t < 9) {
        int u = t / 3, v = t % 3;
        float acc = b1[c];
        #pragma unroll
        for (int i = 0; i < 3; i++)
            #pragma unroll
            for (int j = 0; j < 3; j++)
                acc += avgb[(u + i) * 5 + (v + j)] * w1[c * 9 + i * 3 + j];
        g_wgt1[bc * 9 + t] = fmaxf(acc, 0.f);
    }
}

// ============================================================================
// Kernel 2: dynamic-weight generation.
//   W[b][p][q][tap] = (wgt1[b,p,tap]*w2[p*256+q] + b2[p*256+q])
//                   * sigmoid( conv3x3(maxi[b,p], w_att[p*256+q]) + b_att[..] )
// grid = (256 p, 32 b), 256 threads (q). Writes 9 contiguous floats/thread.
// ============================================================================
__global__ __launch_bounds__(256) void gen_kernel(
    const float* __restrict__ w2,
    const float* __restrict__ b2,
    const float* __restrict__ w_att,
    const float* __restrict__ b_att)
{
    int p = blockIdx.x;
    int b = blockIdx.y;
    int q = threadIdx.x;
    int bp = b * CH + p;

    __shared__ float maxi_s[25];
    __shared__ float wgt1_s[9];
    if (q < 25) maxi_s[q] = g_maxi[bp * 25 + q];
    if (q >= 32 && q < 41) wgt1_s[q - 32] = g_wgt1[bp * 9 + (q - 32)];
    __syncthreads();

    int cidx = p * CH + q;
    float wa[9];
    #pragma unroll
    for (int k = 0; k < 9; k++) wa[k] = w_att[cidx * 9 + k];
    float w2c = w2[cidx], b2c = b2[cidx], bac = b_att[cidx];

    float* outp = g_W + (size_t)bp * CH * 9 + q * 9;
    #pragma unroll
    for (int u = 0; u < 3; u++)
        #pragma unroll
        for (int v = 0; v < 3; v++) {
            float s = bac;
            #pragma unroll
            for (int i = 0; i < 3; i++)
                #pragma unroll
                for (int j = 0; j < 3; j++)
                    s += maxi_s[(u + i) * 5 + (v + j)] * wa[i * 3 + j];
            float att = 1.f / (1.f + __expf(-s));
            outp[u * 3 + v] = (wgt1_s[u * 3 + v] * w2c + b2c) * att;
        }
}

// ============================================================================
// Kernel 3: per-sample dynamic 3x3 conv (pad 1, stride 1).
//   out[b,f,y,x] = sum_{q,i,j} x[b,q,y-1+i,x-1+j] * W[b][f][q][i*3+j]
// Implicit-GEMM tiling: block = (batch b, 128 filters, 2 output rows x 56 cols)
// 256 threads; each thread: 8 filters x 7 cols in registers (56 accums).
// c loop in chunks of 8 staged through shared memory.
// ============================================================================
#define TFILT 128
#define TROWS 2
#define CCHUNK 8
#define XS_ROWS 4            // TROWS + 2 halo
#define XS_COLS 58           // 56 + 2 halo
#define WS_LD   129          // 128 filters + 1 pad (conflict-free)

__global__ __launch_bounds__(256, 2) void conv_kernel(
    const float* __restrict__ x,
    float* __restrict__ out)
{
    __shared__ float xs[CCHUNK * XS_ROWS * XS_COLS];   // [c][row][col]
    __shared__ float ws[CCHUNK * 9 * WS_LD];           // [c*9+tap][f]

    int rowBase = blockIdx.x * TROWS;
    int fBase   = blockIdx.y * TFILT;
    int b       = blockIdx.z;
    int t  = threadIdx.x;
    int ty = t >> 4;          // 0..15 -> filters ty*8 .. ty*8+7
    int tx = t & 15;
    int rr = tx >> 3;         // 0..1  output row within tile
    int cc = tx & 7;          // cols cc + 8k, k = 0..6

    float acc[8][7];
    #pragma unroll
    for (int i = 0; i < 8; i++)
        #pragma unroll
        for (int k = 0; k < 7; k++) acc[i][k] = 0.f;

    const float* xb = x + (size_t)b * CH * HW;
    const float* wb = g_W + (size_t)(b * CH + fBase) * (CH * 9);

    for (int cb = 0; cb < CH; cb += CCHUNK) {
        // ---- stage x tile: 8 ch x 4 rows x 58 cols (halo, zero padded) ----
        for (int idx = t; idx < CCHUNK * XS_ROWS * XS_COLS; idx += 256) {
            int c_  = idx / (XS_ROWS * XS_COLS);
            int rem = idx - c_ * (XS_ROWS * XS_COLS);
            int row = rem / XS_COLS;
            int col = rem - row * XS_COLS;
            int gr = rowBase - 1 + row;
            int gc = col - 1;
            float v = 0.f;
            if ((unsigned)gr < 56u && (unsigned)gc < 56u)
                v = xb[(cb + c_) * HW + gr * 56 + gc];
            xs[idx] = v;
        }
        // ---- stage W tile: 128 f x (8 c x 9 taps), transposed to [r][f] ----
        for (int idx = t; idx < TFILT * CCHUNK * 9; idx += 256) {
            int f_ = idx / (CCHUNK * 9);
            int r  = idx - f_ * (CCHUNK * 9);
            ws[r * WS_LD + f_] = wb[f_ * (CH * 9) + cb * 9 + r];
        }
        __syncthreads();

        #pragma unroll 1
        for (int c_ = 0; c_ < CCHUNK; c_++) {
            #pragma unroll
            for (int tap = 0; tap < 9; tap++) {
                int i = tap / 3, j = tap % 3;
                const float* xrow = &xs[(c_ * XS_ROWS + rr + i) * XS_COLS + cc + j];
                float xv[7];
                #pragma unroll
                for (int k = 0; k < 7; k++) xv[k] = xrow[8 * k];
                const float* wrow = &ws[(c_ * 9 + tap) * WS_LD + ty * 8];
                float wv[8];
                #pragma unroll
                for (int ii = 0; ii < 8; ii++) wv[ii] = wrow[ii];
                #pragma unroll
                for (int ii = 0; ii < 8; ii++)
                    #pragma unroll
                    for (int k = 0; k < 7; k++)
                        acc[ii][k] = fmaf(wv[ii], xv[k], acc[ii][k]);
            }
        }
        __syncthreads();
    }

    // ---- write 8 filters x 7 cols ----
    float* ob = out + (size_t)(b * CH + fBase) * HW + (rowBase + rr) * 56;
    #pragma unroll
    for (int ii = 0; ii < 8; ii++) {
        float* orow = ob + (ty * 8 + ii) * HW;
        #pragma unroll
        for (int k = 0; k < 7; k++)
            orow[cc + 8 * k] = acc[ii][k];
    }
}

// ============================================================================
// launch
// inputs (metadata order): x, w1, b1, w2, b2, w_att, b_att
// ============================================================================
extern "C" void kernel_launch(void* const* d_in, const int* in_sizes, int n_in,
                              void* d_out, int out_size)
{
    const float* x     = (const float*)d_in[0];
    const float* w1    = (const float*)d_in[1];
    const float* b1    = (const float*)d_in[2];
    const float* w2    = (const float*)d_in[3];
    const float* b2    = (const float*)d_in[4];
    const float* w_att = (const float*)d_in[5];
    const float* b_att = (const float*)d_in[6];
    float* out = (float*)d_out;

    pool_kernel<<<BATCH * CH, 128>>>(x, w1, b1);

    dim3 ggrid(CH, BATCH);
    gen_kernel<<<ggrid, 256>>>(w2, b2, w_att, b_att);

    dim3 cgrid(56 / TROWS, CH / TFILT, BATCH);   // 28 x 2 x 32
    conv_kernel<<<cgrid, 256>>>(x, out);
}

// round 6
// speedup vs baseline: 5.6563x; 3.5632x over previous
#include <cuda_runtime.h>
#include <cstdint>

#define BATCH 32
#define CH    256
#define HW    3136

// ---------------- scratch (device globals; no runtime allocation) ----------
__device__ float g_maxi[BATCH * CH * 25];                 // 5x5 max-pool bins
__device__ float g_wgt1[BATCH * CH * 9];                  // relu(dw3x3(avg)+b1)
__device__ float g_W[(size_t)BATCH * CH * 9 * CH];        // [b][f][tap][c]

__constant__ int c_bin_start[5] = {0, 11, 22, 33, 44};
__constant__ int c_bin_end[5]   = {12, 23, 34, 45, 56};

// ============================================================================
// Kernel 1: adaptive avg+max pool 56x56 -> 5x5, fused depthwise 3x3+relu
// ============================================================================
__global__ __launch_bounds__(128) void pool_kernel(
    const float* __restrict__ x, const float* __restrict__ w1,
    const float* __restrict__ b1)
{
    __shared__ float img[HW];
    __shared__ float avgb[25];
    int bc = blockIdx.x, c = bc & 255, t = threadIdx.x;

    const float4* src4 = (const float4*)(x + (size_t)bc * HW);
    float4* img4 = (float4*)img;
    for (int i = t; i < HW / 4; i += 128) img4[i] = src4[i];
    __syncthreads();

    if (t < 25) {
        int bi = t / 5, bj = t % 5;
        int r0 = c_bin_start[bi], r1 = c_bin_end[bi];
        int c0 = c_bin_start[bj], c1 = c_bin_end[bj];
        float s = 0.f, m = -3.402823466e38f;
        for (int r = r0; r < r1; r++) {
            const float* row = img + r * 56;
            for (int cc = c0; cc < c1; cc++) {
                float v = row[cc];
                s += v; m = fmaxf(m, v);
            }
        }
        avgb[t] = s * (1.f / 144.f);
        g_maxi[bc * 25 + t] = m;
    }
    __syncthreads();

    if (t < 9) {
        int u = t / 3, v = t % 3;
        float acc = b1[c];
        #pragma unroll
        for (int i = 0; i < 3; i++)
            #pragma unroll
            for (int j = 0; j < 3; j++)
                acc += avgb[(u + i) * 5 + (v + j)] * w1[c * 9 + i * 3 + j];
        g_wgt1[bc * 9 + t] = fmaxf(acc, 0.f);
    }
}

// ============================================================================
// Kernel 2: weight generation -> g_W[b][f=p][tap][q]  (tap-major K layout)
// ============================================================================
__global__ __launch_bounds__(256) void gen_kernel(
    const float* __restrict__ w2, const float* __restrict__ b2,
    const float* __restrict__ w_att, const float* __restrict__ b_att)
{
    int p = blockIdx.x, b = blockIdx.y, q = threadIdx.x;
    int bp = b * CH + p;

    __shared__ float maxi_s[25];
    __shared__ float wgt1_s[9];
    if (q < 25) maxi_s[q] = g_maxi[bp * 25 + q];
    if (q >= 32 && q < 41) wgt1_s[q - 32] = g_wgt1[bp * 9 + (q - 32)];
    __syncthreads();

    int cidx = p * CH + q;
    float wa[9];
    #pragma unroll
    for (int k = 0; k < 9; k++) wa[k] = w_att[cidx * 9 + k];
    float w2c = w2[cidx], b2c = b2[cidx], bac = b_att[cidx];

    float* outp = g_W + (size_t)bp * 9 * CH;
    #pragma unroll
    for (int u = 0; u < 3; u++)
        #pragma unroll
        for (int v = 0; v < 3; v++) {
            float s = bac;
            #pragma unroll
            for (int i = 0; i < 3; i++)
                #pragma unroll
                for (int j = 0; j < 3; j++)
                    s += maxi_s[(u + i) * 5 + (v + j)] * wa[i * 3 + j];
            float att = 1.f / (1.f + __expf(-s));
            outp[(u * 3 + v) * CH + q] = (wgt1_s[u * 3 + v] * w2c + b2c) * att;
        }
}

// ============================================================================
// helpers: tf32 convert, mma.sync m16n8k8, cp.async
// ============================================================================
__device__ __forceinline__ uint32_t smem_u32(const void* p) {
    uint32_t a;
    asm("{ .reg .u64 t; cvta.to.shared.u64 t, %1; cvt.u32.u64 %0, t; }" : "=r"(a) : "l"(p));
    return a;
}
__device__ __forceinline__ uint32_t f2tf(float f) {
    uint32_t r;
    asm("cvt.rna.tf32.f32 %0, %1;" : "=r"(r) : "f"(f));
    return r;
}
__device__ __forceinline__ void mma8(float* d, const uint32_t* a,
                                     uint32_t b0, uint32_t b1) {
    asm volatile(
        "mma.sync.aligned.m16n8k8.row.col.f32.tf32.tf32.f32 "
        "{%0,%1,%2,%3}, {%4,%5,%6,%7}, {%8,%9}, {%0,%1,%2,%3};"
        : "+f"(d[0]), "+f"(d[1]), "+f"(d[2]), "+f"(d[3])
        : "r"(a[0]), "r"(a[1]), "r"(a[2]), "r"(a[3]), "r"(b0), "r"(b1));
}
__device__ __forceinline__ void cpasync16(uint32_t dst, const void* src) {
    asm volatile("cp.async.cg.shared.global [%0], [%1], 16;" :: "r"(dst), "l"(src));
}
#define CP_COMMIT() asm volatile("cp.async.commit_group;" ::: "memory")
#define CP_WAIT0()  asm volatile("cp.async.wait_group 0;" ::: "memory")

// ============================================================================
// Kernel 3: dynamic conv as tf32 mma.sync implicit GEMM.
// CTA = (b, 128 filters, 4 rows x 56 px). Warps 4(M) x 2(N): 32 x 112 each.
// K = (tap, channel) in 32-chunks; B frags read directly from a padded
// tf32-converted x window (stride 360: channel stride % 32 == 8 -> no
// bank conflicts); A (128x32, stride 36 -> conflict-free) double-buffered
// via cp.async prefetch.
// ============================================================================
#define XW_STR 360                 // 6*58=348 padded; %32==8
#define OFF_A  46080               // xw = 32*360*4 = 46080 B
#define A_BUF  18432               // 128 * 36 * 4
#define CONV_SMEM (OFF_A + 2 * A_BUF)   // 82944 B

__global__ void __launch_bounds__(256, 1)
conv_mma(const float* __restrict__ x, float* __restrict__ out)
{
    extern __shared__ char smem[];
    float* xw = (float*)smem;
    const uint32_t sb = smem_u32(smem);
    const int tid = threadIdx.x, lid = tid & 31, wid = tid >> 5;
    const int g = lid >> 2, t4 = lid & 3;
    const int warpM = wid & 3, warpN = wid >> 2;
    const int b = blockIdx.z, fBase = blockIdx.y * 128, row0 = blockIdx.x * 4;

    const float* xb = x + (size_t)b * CH * HW;
    const float* wb = g_W + (size_t)(b * CH + fBase) * (9 * CH);

    float d[2][14][4];
    #pragma unroll
    for (int i = 0; i < 2; i++)
        #pragma unroll
        for (int j = 0; j < 14; j++)
            #pragma unroll
            for (int k = 0; k < 4; k++) d[i][j][k] = 0.f;

    // ---- A stage: 128 f x 32 k as [f][36] via cp.async (16B granules) ----
    auto stageA = [&](int cg, int tap, int buf) {
        const float* src0 = wb + tap * CH + cg * 32;
        uint32_t dbase = sb + OFF_A + (uint32_t)buf * A_BUF;
        #pragma unroll
        for (int i = 0; i < 4; ++i) {
            int idx = tid + i * 256;          // 0..1023
            int f = idx >> 3, c4 = idx & 7;
            cpasync16(dbase + (uint32_t)f * 144 + (uint32_t)c4 * 16,
                      src0 + (size_t)f * (9 * CH) + c4 * 4);
        }
        CP_COMMIT();
    };

    stageA(0, 0, 0);   // prologue

    for (int cg = 0; cg < 8; ++cg) {
        // ---- build padded tf32 x window: 32 ch x 6 rows x 58 cols ----
        __syncthreads();                       // prev cg compute done with xw
        for (int i = tid; i < (32 * XW_STR) / 4; i += 256)
            ((float4*)xw)[i] = make_float4(0.f, 0.f, 0.f, 0.f);
        __syncthreads();
        for (int i = tid; i < 32 * 6 * 14; i += 256) {
            int c2 = i / 84, rem = i - c2 * 84;
            int rw = rem / 14, gq = rem - rw * 14;
            int grow = row0 - 1 + rw;
            if ((unsigned)grow < 56u) {
                float4 v = *(const float4*)(xb + (size_t)(cg * 32 + c2) * HW
                                            + grow * 56 + 4 * gq);
                float* dst = xw + c2 * XW_STR + rw * 58 + 4 * gq + 1;
                dst[0] = __uint_as_float(f2tf(v.x));
                dst[1] = __uint_as_float(f2tf(v.y));
                dst[2] = __uint_as_float(f2tf(v.z));
                dst[3] = __uint_as_float(f2tf(v.w));
            }
        }
        __syncthreads();

        for (int tap = 0; tap < 9; ++tap) {
            const int chunk = cg * 9 + tap;
            const int buf = chunk & 1;
            CP_WAIT0();
            __syncthreads();                   // A[buf] visible to all
            if (chunk < 71) {
                int nc = chunk + 1;
                stageA(nc / 9, nc % 9, buf ^ 1);
            }
            const int ti = tap / 3, tj = tap - ti * 3;
            const float* as = (const float*)(smem + OFF_A + buf * A_BUF);

            #pragma unroll
            for (int ks = 0; ks < 4; ++ks) {
                const int k0 = ks * 8;
                uint32_t A[2][4];
                #pragma unroll
                for (int mf = 0; mf < 2; ++mf) {
                    int fr = warpM * 32 + mf * 16;
                    A[mf][0] = f2tf(as[(fr + g) * 36 + k0 + t4]);
                    A[mf][1] = f2tf(as[(fr + 8 + g) * 36 + k0 + t4]);
                    A[mf][2] = f2tf(as[(fr + g) * 36 + k0 + t4 + 4]);
                    A[mf][3] = f2tf(as[(fr + 8 + g) * 36 + k0 + t4 + 4]);
                }
                const float* bbase = xw + (k0 + t4) * XW_STR + ti * 58 + tj + g;
                #pragma unroll
                for (int nf = 0; nf < 14; ++nf) {
                    const float* bp = bbase + (warpN * 2 + nf / 7) * 58
                                    + (nf % 7) * 8;
                    uint32_t b0 = __float_as_uint(bp[0]);
                    uint32_t b1 = __float_as_uint(bp[4 * XW_STR]);
                    mma8(d[0][nf], A[0], b0, b1);
                    mma8(d[1][nf], A[1], b0, b1);
                }
            }
        }
    }

    // ---- epilogue: fragment (row g / g+8, cols 2*t4, 2*t4+1) -> float2 ----
    #pragma unroll
    for (int mf = 0; mf < 2; ++mf) {
        int mrow = fBase + warpM * 32 + mf * 16 + g;
        float* o0 = out + (size_t)(b * CH + mrow) * HW + row0 * 56;
        float* o8 = o0 + 8 * (size_t)HW;
        #pragma unroll
        for (int nf = 0; nf < 14; ++nf) {
            int pix = warpN * 112 + nf * 8 + 2 * t4;
            *(float2*)(o0 + pix) = make_float2(d[mf][nf][0], d[mf][nf][1]);
            *(float2*)(o8 + pix) = make_float2(d[mf][nf][2], d[mf][nf][3]);
        }
    }
}

// ============================================================================
// launch — inputs: x, w1, b1, w2, b2, w_att, b_att
// ============================================================================
extern "C" void kernel_launch(void* const* d_in, const int* in_sizes, int n_in,
                              void* d_out, int out_size)
{
    const float* x     = (const float*)d_in[0];
    const float* w1    = (const float*)d_in[1];
    const float* b1    = (const float*)d_in[2];
    const float* w2    = (const float*)d_in[3];
    const float* b2    = (const float*)d_in[4];
    const float* w_att = (const float*)d_in[5];
    const float* b_att = (const float*)d_in[6];
    float* out = (float*)d_out;

    cudaFuncSetAttribute(conv_mma, cudaFuncAttributeMaxDynamicSharedMemorySize,
                         CONV_SMEM);

    pool_kernel<<<BATCH * CH, 128>>>(x, w1, b1);
    dim3 ggrid(CH, BATCH);
    gen_kernel<<<ggrid, 256>>>(w2, b2, w_att, b_att);
    dim3 cgrid(14, 2, BATCH);
    conv_mma<<<cgrid, 256, CONV_SMEM>>>(x, out);
}

// round 7
// speedup vs baseline: 7.9589x; 1.4071x over previous
#include <cuda_runtime.h>
#include <cstdint>

#define BATCH 32
#define CH    256
#define HW    3136

// ---------------- scratch (device globals; no runtime allocation) ----------
__device__ float g_maxi[BATCH * CH * 25];                 // 5x5 max-pool bins
__device__ float g_wgt1[BATCH * CH * 9];                  // relu(dw3x3(avg)+b1)
__device__ float g_W[(size_t)BATCH * CH * 9 * CH];        // [b][f][tap][c], tf32-rounded

__constant__ int c_bin_start[5] = {0, 11, 22, 33, 44};

__device__ __forceinline__ uint32_t f2tf(float f) {
    uint32_t r;
    asm("cvt.rna.tf32.f32 %0, %1;" : "=r"(r) : "f"(f));
    return r;
}

// ============================================================================
// Kernel 1: adaptive avg+max pool 56x56 -> 5x5, fused depthwise 3x3+relu.
// Two-stage parallel reduction (row bands, then column bins).
// ============================================================================
__global__ __launch_bounds__(256) void pool_kernel(
    const float* __restrict__ x, const float* __restrict__ w1,
    const float* __restrict__ b1)
{
    __shared__ float img[HW];
    __shared__ float rs[5][56], rm[5][56];
    __shared__ float avgb[25];
    int bc = blockIdx.x, c = bc & 255, t = threadIdx.x;

    const float4* src4 = (const float4*)(x + (size_t)bc * HW);
    float4* img4 = (float4*)img;
    for (int i = t; i < HW / 4; i += 256) img4[i] = src4[i];
    __syncthreads();

    // stage 1: 5 bands x 56 cols, each reduces 12 rows
    for (int t2 = t; t2 < 280; t2 += 256) {
        int band = t2 / 56, col = t2 - band * 56;
        int r0 = c_bin_start[band];
        float s = 0.f, m = -3.402823466e38f;
        #pragma unroll
        for (int r = 0; r < 12; r++) {
            float v = img[(r0 + r) * 56 + col];
            s += v; m = fmaxf(m, v);
        }
        rs[band][col] = s; rm[band][col] = m;
    }
    __syncthreads();

    // stage 2: 25 bins, each reduces 12 band-columns
    if (t < 25) {
        int bi = t / 5, bj = t % 5;
        int c0 = c_bin_start[bj];
        float s = 0.f, m = -3.402823466e38f;
        #pragma unroll
        for (int k = 0; k < 12; k++) {
            s += rs[bi][c0 + k];
            m = fmaxf(m, rm[bi][c0 + k]);
        }
        avgb[t] = s * (1.f / 144.f);
        g_maxi[bc * 25 + t] = m;
    }
    __syncthreads();

    if (t < 9) {
        int u = t / 3, v = t % 3;
        float acc = b1[c];
        #pragma unroll
        for (int i = 0; i < 3; i++)
            #pragma unroll
            for (int j = 0; j < 3; j++)
                acc += avgb[(u + i) * 5 + (v + j)] * w1[c * 9 + i * 3 + j];
        g_wgt1[bc * 9 + t] = fmaxf(acc, 0.f);
    }
}

// ============================================================================
// Kernel 2: weight generation -> g_W[b][f=p][tap][q], rounded to tf32
// ============================================================================
__global__ __launch_bounds__(256) void gen_kernel(
    const float* __restrict__ w2, const float* __restrict__ b2,
    const float* __restrict__ w_att, const float* __restrict__ b_att)
{
    int p = blockIdx.x, b = blockIdx.y, q = threadIdx.x;
    int bp = b * CH + p;

    __shared__ float maxi_s[25];
    __shared__ float wgt1_s[9];
    if (q < 25) maxi_s[q] = g_maxi[bp * 25 + q];
    if (q >= 32 && q < 41) wgt1_s[q - 32] = g_wgt1[bp * 9 + (q - 32)];
    __syncthreads();

    int cidx = p * CH + q;
    float wa[9];
    #pragma unroll
    for (int k = 0; k < 9; k++) wa[k] = w_att[cidx * 9 + k];
    float w2c = w2[cidx], b2c = b2[cidx], bac = b_att[cidx];

    float* outp = g_W + (size_t)bp * 9 * CH;
    #pragma unroll
    for (int u = 0; u < 3; u++)
        #pragma unroll
        for (int v = 0; v < 3; v++) {
            float s = bac;
            #pragma unroll
            for (int i = 0; i < 3; i++)
                #pragma unroll
                for (int j = 0; j < 3; j++)
                    s += maxi_s[(u + i) * 5 + (v + j)] * wa[i * 3 + j];
            float att = 1.f / (1.f + __expf(-s));
            outp[(u * 3 + v) * CH + q] =
                __uint_as_float(f2tf((wgt1_s[u * 3 + v] * w2c + b2c) * att));
        }
}

// ============================================================================
// helpers: mma.sync m16n8k8 tf32, cp.async
// ============================================================================
__device__ __forceinline__ uint32_t smem_u32(const void* p) {
    uint32_t a;
    asm("{ .reg .u64 t; cvta.to.shared.u64 t, %1; cvt.u32.u64 %0, t; }" : "=r"(a) : "l"(p));
    return a;
}
__device__ __forceinline__ void mma8(float* d, const uint32_t* a,
                                     uint32_t b0, uint32_t b1) {
    asm volatile(
        "mma.sync.aligned.m16n8k8.row.col.f32.tf32.tf32.f32 "
        "{%0,%1,%2,%3}, {%4,%5,%6,%7}, {%8,%9}, {%0,%1,%2,%3};"
        : "+f"(d[0]), "+f"(d[1]), "+f"(d[2]), "+f"(d[3])
        : "r"(a[0]), "r"(a[1]), "r"(a[2]), "r"(a[3]), "r"(b0), "r"(b1));
}
__device__ __forceinline__ void cpasync16(uint32_t dst, const void* src) {
    asm volatile("cp.async.cg.shared.global [%0], [%1], 16;" :: "r"(dst), "l"(src));
}
#define CP_COMMIT() asm volatile("cp.async.commit_group;" ::: "memory")
#define CP_WAIT0()  asm volatile("cp.async.wait_group 0;" ::: "memory")

// ============================================================================
// Kernel 3: dynamic conv as tf32 mma.sync implicit GEMM.
// CTA = (b, 128 filters, 4 rows x 56 px). Warps 4(M) x 2(N): 32 x 112 each.
// K = (tap, channel): cg loop of 32 channels; within a cg, three A stages of
// 3 taps (K=96) double-buffered via cp.async; next cg's x window prefetched
// raw via cp.async and converted to a padded tf32 window SMEM->SMEM.
// All cp.async waits are wait_group 0 with exactly the needed group pending.
// ============================================================================
#define XW_STR  360                // padded window stride (%32==8, conflict-free)
#define OFF_XR  46080              // xw: 32*360*4
#define XR_SZ   43008              // xraw: 32*6*56*4
#define OFF_A   89088
#define A_STR   108                // floats per filter row (3 taps*32 + 12 pad)
#define A_BUF   55296              // 128*108*4
#define CONV_SMEM (OFF_A + 2 * A_BUF)   // 199680 B

__global__ void __launch_bounds__(256, 1)
conv_mma(const float* __restrict__ x, float* __restrict__ out)
{
    extern __shared__ char smem[];
    float* xw = (float*)smem;
    float* xraw = (float*)(smem + OFF_XR);
    const uint32_t sb = smem_u32(smem);
    const int tid = threadIdx.x, lid = tid & 31, wid = tid >> 5;
    const int g = lid >> 2, t4 = lid & 3;
    const int warpM = wid & 3, warpN = wid >> 2;
    const int b = blockIdx.z, fBase = blockIdx.y * 128, row0 = blockIdx.x * 4;

    const float* xb = x + (size_t)b * CH * HW;
    const float* wb = g_W + (size_t)(b * CH + fBase) * (9 * CH);

    float d[2][14][4];
    #pragma unroll
    for (int i = 0; i < 2; i++)
        #pragma unroll
        for (int j = 0; j < 14; j++)
            #pragma unroll
            for (int k = 0; k < 4; k++) d[i][j][k] = 0.f;

    // ---- A stage: 128 f x 96 k (3 taps), [f][108] layout ----
    auto stageA = [&](int stageIdx, int buf) {
        int scg = stageIdx / 3, ss = stageIdx - scg * 3;
        const float* src0 = wb + (ss * 3) * CH + scg * 32;
        uint32_t dbase = sb + OFF_A + (uint32_t)buf * A_BUF;
        #pragma unroll
        for (int i = 0; i < 12; ++i) {
            int idx = i * 256 + tid;           // 0..3071
            int f = idx / 24, r = idx - f * 24;
            int tapo = r >> 3, c4 = r & 7;
            cpasync16(dbase + (uint32_t)f * 432 + (uint32_t)(tapo * 128 + c4 * 16),
                      src0 + (size_t)f * (9 * CH) + tapo * CH + c4 * 4);
        }
        CP_COMMIT();
    };
    // ---- X prefetch: raw window for channel group cg -> xraw ----
    auto stageX = [&](int cg) {
        for (int i = tid; i < 32 * 84; i += 256) {
            int c2 = i / 84, rem = i - c2 * 84;
            int rw = rem / 14, gq = rem - rw * 14;
            int grow = row0 - 1 + rw;
            if ((unsigned)grow < 56u)
                cpasync16(sb + OFF_XR + (uint32_t)i * 16,
                          xb + (size_t)(cg * 32 + c2) * HW + grow * 56 + 4 * gq);
        }
        CP_COMMIT();
    };

    // ---- prologue: zero xw once (halo stays zero forever), prefetch ----
    for (int i = tid; i < (32 * XW_STR) / 4; i += 256)
        ((float4*)xw)[i] = make_float4(0.f, 0.f, 0.f, 0.f);
    stageX(0);
    stageA(0, 0);
    // NOTE: X committed before A(0): prologue top wait is wait-all anyway.

    int stage = 0;
    for (int cg = 0; cg < 8; ++cg) {
        CP_WAIT0();
        __syncthreads();
        // ---- convert raw window -> padded tf32 window ----
        for (int i = tid; i < 32 * 84; i += 256) {
            int c2 = i / 84, rem = i - c2 * 84;
            int rw = rem / 14, gq = rem - rw * 14;
            int grow = row0 - 1 + rw;
            if ((unsigned)grow < 56u) {
                float4 v = ((const float4*)xraw)[i];
                float* dst = xw + c2 * XW_STR + rw * 58 + 4 * gq + 1;
                dst[0] = __uint_as_float(f2tf(v.x));
                dst[1] = __uint_as_float(f2tf(v.y));
                dst[2] = __uint_as_float(f2tf(v.z));
                dst[3] = __uint_as_float(f2tf(v.w));
            }
        }
        __syncthreads();

        for (int s = 0; s < 3; ++s, ++stage) {
            const int buf = stage & 1;
            if (s > 0) {                       // A[buf] pending from prev stage
                CP_WAIT0();
                __syncthreads();
            }
            // prefetch: keep at most ONE A group pending at any wait point;
            // X is committed only after this cg's last intra-cg A commit.
            if (s < 2) {
                stageA(stage + 1, buf ^ 1);
            } else {
                if (cg < 7) stageX(cg + 1);
                if (stage + 1 < 24) stageA(stage + 1, buf ^ 1);
            }

            const float* as = (const float*)(smem + OFF_A + buf * A_BUF);
            #pragma unroll
            for (int tapo = 0; tapo < 3; ++tapo) {
                const int tap = s * 3 + tapo;
                const int ti = tap / 3, tj = tap - ti * 3;
                #pragma unroll
                for (int ks = 0; ks < 4; ++ks) {
                    const int k0 = ks * 8;
                    uint32_t A[2][4];
                    #pragma unroll
                    for (int mf = 0; mf < 2; ++mf) {
                        int fr = warpM * 32 + mf * 16;
                        const float* a0 = as + (fr + g) * A_STR + tapo * 32 + k0 + t4;
                        const float* a8 = a0 + 8 * A_STR;
                        A[mf][0] = __float_as_uint(a0[0]);
                        A[mf][1] = __float_as_uint(a8[0]);
                        A[mf][2] = __float_as_uint(a0[4]);
                        A[mf][3] = __float_as_uint(a8[4]);
                    }
                    const float* bbase = xw + (k0 + t4) * XW_STR + ti * 58 + tj + g;
                    #pragma unroll
                    for (int nf = 0; nf < 14; ++nf) {
                        const float* bp = bbase + (warpN * 2 + nf / 7) * 58
                                        + (nf % 7) * 8;
                        uint32_t b0 = __float_as_uint(bp[0]);
                        uint32_t b1 = __float_as_uint(bp[4 * XW_STR]);
                        mma8(d[0][nf], A[0], b0, b1);
                        mma8(d[1][nf], A[1], b0, b1);
                    }
                }
            }
        }
    }

    // ---- epilogue ----
    #pragma unroll
    for (int mf = 0; mf < 2; ++mf) {
        int mrow = fBase + warpM * 32 + mf * 16 + g;
        float* o0 = out + (size_t)(b * CH + mrow) * HW + row0 * 56;
        float* o8 = o0 + 8 * (size_t)HW;
        #pragma unroll
        for (int nf = 0; nf < 14; ++nf) {
            int pix = warpN * 112 + nf * 8 + 2 * t4;
            *(float2*)(o0 + pix) = make_float2(d[mf][nf][0], d[mf][nf][1]);
            *(float2*)(o8 + pix) = make_float2(d[mf][nf][2], d[mf][nf][3]);
        }
    }
}

// ============================================================================
// launch — inputs: x, w1, b1, w2, b2, w_att, b_att
// ============================================================================
extern "C" void kernel_launch(void* const* d_in, const int* in_sizes, int n_in,
                              void* d_out, int out_size)
{
    const float* x     = (const float*)d_in[0];
    const float* w1    = (const float*)d_in[1];
    const float* b1    = (const float*)d_in[2];
    const float* w2    = (const float*)d_in[3];
    const float* b2    = (const float*)d_in[4];
    const float* w_att = (const float*)d_in[5];
    const float* b_att = (const float*)d_in[6];
    float* out = (float*)d_out;

    cudaFuncSetAttribute(conv_mma, cudaFuncAttributeMaxDynamicSharedMemorySize,
                         CONV_SMEM);

    pool_kernel<<<BATCH * CH, 256>>>(x, w1, b1);
    dim3 ggrid(CH, BATCH);
    gen_kernel<<<ggrid, 256>>>(w2, b2, w_att, b_att);
    dim3 cgrid(14, 2, BATCH);
    conv_mma<<<cgrid, 256, CONV_SMEM>>>(x, out);
}

// round 9
// speedup vs baseline: 8.6831x; 1.0910x over previous
#include <cuda_runtime.h>
#include <cstdint>

#define BATCH 32
#define CH    256
#define HW    3136

// per-(b, f_half) stride in g_W: 288 k_tiles * 8 f_tiles * 128 = 294912 floats
#define WHALF 294912ull

// ---------------- scratch (device globals; no runtime allocation) ----------
__device__ float g_maxi[BATCH * CH * 25];                 // 5x5 max-pool bins
__device__ float g_wgt1[BATCH * CH * 9];                  // relu(dw3x3(avg)+b1)
// g_W in MMA-fragment order: [b][f_half(2)][k_tile(288)][f_tile(8)][lane(32)][reg(4)]
// k = (cg*9 + tap)*32 + ci ; k_tile = k/8 ; values tf32-pre-rounded.
__device__ float g_W[(size_t)BATCH * CH * 9 * CH];

__constant__ int c_bin_start[5] = {0, 11, 22, 33, 44};

__device__ __forceinline__ uint32_t f2tf(float f) {
    uint32_t r;
    asm("cvt.rna.tf32.f32 %0, %1;" : "=r"(r) : "f"(f));
    return r;
}

// ============================================================================
// Kernel 1: adaptive avg+max pool 56x56 -> 5x5, fused depthwise 3x3+relu.
// ============================================================================
__global__ __launch_bounds__(256) void pool_kernel(
    const float* __restrict__ x, const float* __restrict__ w1,
    const float* __restrict__ b1)
{
    __shared__ float img[HW];
    __shared__ float rs[5][56], rm[5][56];
    __shared__ float avgb[25];
    int bc = blockIdx.x, c = bc & 255, t = threadIdx.x;

    const float4* src4 = (const float4*)(x + (size_t)bc * HW);
    float4* img4 = (float4*)img;
    for (int i = t; i < HW / 4; i += 256) img4[i] = src4[i];
    __syncthreads();

    for (int t2 = t; t2 < 280; t2 += 256) {
        int band = t2 / 56, col = t2 - band * 56;
        int r0 = c_bin_start[band];
        float s = 0.f, m = -3.402823466e38f;
        #pragma unroll
        for (int r = 0; r < 12; r++) {
            float v = img[(r0 + r) * 56 + col];
            s += v; m = fmaxf(m, v);
        }
        rs[band][col] = s; rm[band][col] = m;
    }
    __syncthreads();

    if (t < 25) {
        int bi = t / 5, bj = t % 5;
        int c0 = c_bin_start[bj];
        float s = 0.f, m = -3.402823466e38f;
        #pragma unroll
        for (int k = 0; k < 12; k++) {
            s += rs[bi][c0 + k];
            m = fmaxf(m, rm[bi][c0 + k]);
        }
        avgb[t] = s * (1.f / 144.f);
        g_maxi[bc * 25 + t] = m;
    }
    __syncthreads();

    if (t < 9) {
        int u = t / 3, v = t % 3;
        float acc = b1[c];
        #pragma unroll
        for (int i = 0; i < 3; i++)
            #pragma unroll
            for (int j = 0; j < 3; j++)
                acc += avgb[(u + i) * 5 + (v + j)] * w1[c * 9 + i * 3 + j];
        g_wgt1[bc * 9 + t] = fmaxf(acc, 0.f);
    }
}

// ============================================================================
// Kernel 2: weight generation, scatter-stored in MMA fragment order, tf32.
// ============================================================================
__global__ __launch_bounds__(256) void gen_kernel(
    const float* __restrict__ w2, const float* __restrict__ b2,
    const float* __restrict__ w_att, const float* __restrict__ b_att)
{
    int p = blockIdx.x, b = blockIdx.y, q = threadIdx.x;
    int bp = b * CH + p;

    __shared__ float maxi_s[25];
    __shared__ float wgt1_s[9];
    if (q < 25) maxi_s[q] = g_maxi[bp * 25 + q];
    if (q >= 32 && q < 41) wgt1_s[q - 32] = g_wgt1[bp * 9 + (q - 32)];
    __syncthreads();

    int cidx = p * CH + q;
    float wa[9];
    #pragma unroll
    for (int k = 0; k < 9; k++) wa[k] = w_att[cidx * 9 + k];
    float w2c = w2[cidx], b2c = b2[cidx], bac = b_att[cidx];

    // fragment-order address components (f = p, channel = q)
    int cg = q >> 5, ci = q & 31;
    int fh = p >> 7, fr = p & 127, ft = fr >> 4;
    int lane = ((p & 7) << 2) | (ci & 3);
    int reg  = ((p >> 3) & 1) | (((ci >> 2) & 1) << 1);
    float* base = g_W + ((size_t)b * 2 + fh) * WHALF;

    #pragma unroll
    for (int u = 0; u < 3; u++)
        #pragma unroll
        for (int v = 0; v < 3; v++) {
            float s = bac;
            #pragma unroll
            for (int i = 0; i < 3; i++)
                #pragma unroll
                for (int j = 0; j < 3; j++)
                    s += maxi_s[(u + i) * 5 + (v + j)] * wa[i * 3 + j];
            float att = 1.f / (1.f + __expf(-s));
            float val = (wgt1_s[u * 3 + v] * w2c + b2c) * att;
            int tap = u * 3 + v;
            int kt = (cg * 9 + tap) * 4 + (ci >> 3);
            base[((size_t)kt * 8 + ft) * 128 + lane * 4 + reg] =
                __uint_as_float(f2tf(val));
        }
}

// ============================================================================
// helpers
// ============================================================================
__device__ __forceinline__ uint32_t smem_u32(const void* p) {
    uint32_t a;
    asm("{ .reg .u64 t; cvta.to.shared.u64 t, %1; cvt.u32.u64 %0, t; }" : "=r"(a) : "l"(p));
    return a;
}
__device__ __forceinline__ void mma8(float* d, const float4 a,
                                     uint32_t b0, uint32_t b1) {
    asm volatile(
        "mma.sync.aligned.m16n8k8.row.col.f32.tf32.tf32.f32 "
        "{%0,%1,%2,%3}, {%4,%5,%6,%7}, {%8,%9}, {%0,%1,%2,%3};"
        : "+f"(d[0]), "+f"(d[1]), "+f"(d[2]), "+f"(d[3])
        : "r"(__float_as_uint(a.x)), "r"(__float_as_uint(a.y)),
          "r"(__float_as_uint(a.z)), "r"(__float_as_uint(a.w)),
          "r"(b0), "r"(b1));
}
__device__ __forceinline__ void cpasync16(uint32_t dst, const void* src) {
    asm volatile("cp.async.cg.shared.global [%0], [%1], 16;" :: "r"(dst), "l"(src));
}
#define CP_COMMIT() asm volatile("cp.async.commit_group;" ::: "memory")
#define CP_WAIT0()  asm volatile("cp.async.wait_group 0;" ::: "memory")

// ============================================================================
// Kernel 3: tf32 mma.sync implicit GEMM, fragment-order A.
// CTA = (b, f_half 128 filters, 4 rows x 56 px). Warps 2(M) x 4(N):
// warp tile = 64 filters x 56 px (4 m-frags x 7 n-frags).
// A stage = 3 taps = 12 k_tiles = 48KB CONTIGUOUS cp.async copy.
// A fragment = one LDS.128. B read from padded tf32 x window.
// ============================================================================
#define XW_STR  360
#define OFF_XR  46080              // xw: 32*360*4
#define OFF_A   89088              // xraw: 32*84*16 = 43008
#define A_BUF   49152              // 12 kt * 8 ft * 128 * 4B
#define CONV_SMEM (OFF_A + 2 * A_BUF)   // 187392 B

__global__ void __launch_bounds__(256, 1)
conv_mma(const float* __restrict__ x, float* __restrict__ out)
{
    extern __shared__ char smem[];
    float* xw = (float*)smem;
    float* xraw = (float*)(smem + OFF_XR);
    const uint32_t sb = smem_u32(smem);
    const int tid = threadIdx.x, lid = tid & 31, wid = tid >> 5;
    const int g = lid >> 2, t4 = lid & 3;
    const int warpM = wid & 1, warpN = wid >> 1;    // 2 x 4
    const int b = blockIdx.z, fh = blockIdx.y, row0 = blockIdx.x * 4;

    const float* xb = x + (size_t)b * CH * HW;
    const float* wb = g_W + ((size_t)b * 2 + fh) * WHALF;

    float d[4][7][4];
    #pragma unroll
    for (int i = 0; i < 4; i++)
        #pragma unroll
        for (int j = 0; j < 7; j++)
            #pragma unroll
            for (int k = 0; k < 4; k++) d[i][j][k] = 0.f;

    // ---- A stage: 48KB linear copy (stage = 3 taps of one cg) ----
    auto stageA = [&](int stageIdx, int buf) {
        const float* src = wb + (size_t)stageIdx * 12288;
        uint32_t dbase = sb + OFF_A + (uint32_t)buf * A_BUF;
        #pragma unroll
        for (int i = 0; i < 12; ++i) {
            int idx = i * 256 + tid;
            cpasync16(dbase + (uint32_t)idx * 16, src + idx * 4);
        }
        CP_COMMIT();
    };
    // ---- X prefetch: raw 32-ch window -> xraw ----
    auto stageX = [&](int cg) {
        for (int i = tid; i < 32 * 84; i += 256) {
            int c2 = i / 84, rem = i - c2 * 84;
            int rw = rem / 14, gq = rem - rw * 14;
            int grow = row0 - 1 + rw;
            if ((unsigned)grow < 56u)
                cpasync16(sb + OFF_XR + (uint32_t)i * 16,
                          xb + (size_t)(cg * 32 + c2) * HW + grow * 56 + 4 * gq);
        }
        CP_COMMIT();
    };

    for (int i = tid; i < (32 * XW_STR) / 4; i += 256)
        ((float4*)xw)[i] = make_float4(0.f, 0.f, 0.f, 0.f);
    stageX(0);
    stageA(0, 0);

    int stage = 0;
    for (int cg = 0; cg < 8; ++cg) {
        CP_WAIT0();
        __syncthreads();
        // ---- convert raw window -> padded tf32 window ----
        for (int i = tid; i < 32 * 84; i += 256) {
            int c2 = i / 84, rem = i - c2 * 84;
            int rw = rem / 14, gq = rem - rw * 14;
            int grow = row0 - 1 + rw;
            if ((unsigned)grow < 56u) {
                float4 v = ((const float4*)xraw)[i];
                float* dst = xw + c2 * XW_STR + rw * 58 + 4 * gq + 1;
                dst[0] = __uint_as_float(f2tf(v.x));
                dst[1] = __uint_as_float(f2tf(v.y));
                dst[2] = __uint_as_float(f2tf(v.z));
                dst[3] = __uint_as_float(f2tf(v.w));
            }
        }
        __syncthreads();

        for (int s = 0; s < 3; ++s, ++stage) {
            const int buf = stage & 1;
            if (s > 0) {
                CP_WAIT0();
                __syncthreads();
            }
            if (s < 2) {
                stageA(stage + 1, buf ^ 1);
            } else {
                if (cg < 7) stageX(cg + 1);
                if (stage + 1 < 24) stageA(stage + 1, buf ^ 1);
            }

            const float* as = (const float*)(smem + OFF_A + buf * A_BUF);
            #pragma unroll
            for (int tapo = 0; tapo < 3; ++tapo) {
                const int tap = s * 3 + tapo;
                const int ti = tap / 3, tj = tap - ti * 3;
                #pragma unroll
                for (int ks = 0; ks < 4; ++ks) {
                    // A fragments: one LDS.128 per m-frag
                    float4 A[4];
                    const float* abase = as + ((tapo * 4 + ks) * 8 + warpM * 4) * 128
                                       + lid * 4;
                    #pragma unroll
                    for (int mf = 0; mf < 4; ++mf)
                        A[mf] = *(const float4*)(abase + mf * 128);
                    const float* bbase = xw + (ks * 8 + t4) * XW_STR
                                       + (warpN + ti) * 58 + tj + g;
                    #pragma unroll
                    for (int nf = 0; nf < 7; ++nf) {
                        const float* bp = bbase + nf * 8;
                        uint32_t b0 = __float_as_uint(bp[0]);
                        uint32_t b1 = __float_as_uint(bp[4 * XW_STR]);
                        #pragma unroll
                        for (int mf = 0; mf < 4; ++mf)
                            mma8(d[mf][nf], A[mf], b0, b1);
                    }
                }
            }
        }
    }

    // ---- epilogue ----
    #pragma unroll
    for (int mf = 0; mf < 4; ++mf) {
        int mrow = fh * 128 + (warpM * 4 + mf) * 16 + g;
        float* o0 = out + (size_t)(b * CH + mrow) * HW + (row0 + warpN) * 56;
        float* o8 = o0 + 8 * (size_t)HW;
        #pragma unroll
        for (int nf = 0; nf < 7; ++nf) {
            int pix = nf * 8 + 2 * t4;
            *(float2*)(o0 + pix) = make_float2(d[mf][nf][0], d[mf][nf][1]);
            *(float2*)(o8 + pix) = make_float2(d[mf][nf][2], d[mf][nf][3]);
        }
    }
}

// ============================================================================
// launch — inputs: x, w1, b1, w2, b2, w_att, b_att
// ============================================================================
extern "C" void kernel_launch(void* const* d_in, const int* in_sizes, int n_in,
                              void* d_out, int out_size)
{
    const float* x     = (const float*)d_in[0];
    const float* w1    = (const float*)d_in[1];
    const float* b1    = (const float*)d_in[2];
    const float* w2    = (const float*)d_in[3];
    const float* b2    = (const float*)d_in[4];
    const float* w_att = (const float*)d_in[5];
    const float* b_att = (const float*)d_in[6];
    float* out = (float*)d_out;

    cudaFuncSetAttribute(conv_mma, cudaFuncAttributeMaxDynamicSharedMemorySize,
                         CONV_SMEM);

    pool_kernel<<<BATCH * CH, 256>>>(x, w1, b1);
    dim3 ggrid(CH, BATCH);
    gen_kernel<<<ggrid, 256>>>(w2, b2, w_att, b_att);
    dim3 cgrid(14, 2, BATCH);
    conv_mma<<<cgrid, 256, CONV_SMEM>>>(x, out);
}

// round 10
// speedup vs baseline: 14.0424x; 1.6172x over previous
#include <cuda_runtime.h>
#include <cuda_fp16.h>
#include <cstdint>

#define BATCH 32
#define CH    256
#define HW    3136

// per-(b, f_half) stride in g_W: 144 k16_tiles * 8 f_tiles * 32 lanes * 8 halves
#define WHALF 294912ull

// ---------------- scratch (device globals; no runtime allocation) ----------
__device__ float  g_maxi[BATCH * CH * 25];
__device__ float  g_wgt1[BATCH * CH * 9];
// fp16 weights in m16n8k16 fragment order:
// [b][f_half(2)][k16_tile(144)][f_tile(8)][lane(32)][reg(4)x half(2)]
__device__ __half g_W[(size_t)BATCH * CH * 9 * CH];

__constant__ int c_bin_start[5] = {0, 11, 22, 33, 44};

// ============================================================================
// Kernel 1: adaptive avg+max pool 56x56 -> 5x5, fused depthwise 3x3+relu.
// ============================================================================
__global__ __launch_bounds__(256) void pool_kernel(
    const float* __restrict__ x, const float* __restrict__ w1,
    const float* __restrict__ b1)
{
    __shared__ float img[HW];
    __shared__ float rs[5][56], rm[5][56];
    __shared__ float avgb[25];
    int bc = blockIdx.x, c = bc & 255, t = threadIdx.x;

    const float4* src4 = (const float4*)(x + (size_t)bc * HW);
    float4* img4 = (float4*)img;
    for (int i = t; i < HW / 4; i += 256) img4[i] = src4[i];
    __syncthreads();

    for (int t2 = t; t2 < 280; t2 += 256) {
        int band = t2 / 56, col = t2 - band * 56;
        int r0 = c_bin_start[band];
        float s = 0.f, m = -3.402823466e38f;
        #pragma unroll
        for (int r = 0; r < 12; r++) {
            float v = img[(r0 + r) * 56 + col];
            s += v; m = fmaxf(m, v);
        }
        rs[band][col] = s; rm[band][col] = m;
    }
    __syncthreads();

    if (t < 25) {
        int bi = t / 5, bj = t % 5;
        int c0 = c_bin_start[bj];
        float s = 0.f, m = -3.402823466e38f;
        #pragma unroll
        for (int k = 0; k < 12; k++) {
            s += rs[bi][c0 + k];
            m = fmaxf(m, rm[bi][c0 + k]);
        }
        avgb[t] = s * (1.f / 144.f);
        g_maxi[bc * 25 + t] = m;
    }
    __syncthreads();

    if (t < 9) {
        int u = t / 3, v = t % 3;
        float acc = b1[c];
        #pragma unroll
        for (int i = 0; i < 3; i++)
            #pragma unroll
            for (int j = 0; j < 3; j++)
                acc += avgb[(u + i) * 5 + (v + j)] * w1[c * 9 + i * 3 + j];
        g_wgt1[bc * 9 + t] = fmaxf(acc, 0.f);
    }
}

// ============================================================================
// Kernel 2: weight generation, scatter-stored fp16 in m16n8k16 fragment order.
// k = (cg*9 + tap)*32 + ci ; kt = k/16 ; kk = k%16.
// lane = (f%8)*4 + (kk%8)/2 ; reg = [f%16>=8] + 2*[kk>=8] ; h = kk&1.
// ============================================================================
__global__ __launch_bounds__(256) void gen_kernel(
    const float* __restrict__ w2, const float* __restrict__ b2,
    const float* __restrict__ w_att, const float* __restrict__ b_att)
{
    int p = blockIdx.x, b = blockIdx.y, q = threadIdx.x;
    int bp = b * CH + p;

    __shared__ float maxi_s[25];
    __shared__ float wgt1_s[9];
    if (q < 25) maxi_s[q] = g_maxi[bp * 25 + q];
    if (q >= 32 && q < 41) wgt1_s[q - 32] = g_wgt1[bp * 9 + (q - 32)];
    __syncthreads();

    int cidx = p * CH + q;
    float wa[9];
    #pragma unroll
    for (int k = 0; k < 9; k++) wa[k] = w_att[cidx * 9 + k];
    float w2c = w2[cidx], b2c = b2[cidx], bac = b_att[cidx];

    int cg = q >> 5, ci = q & 31;
    int fh = p >> 7, fr = p & 127, ft = fr >> 4;
    int kk = ci & 15;
    int lane = ((fr & 7) << 2) | ((kk & 7) >> 1);
    int reg  = ((fr >> 3) & 1) | ((kk >> 3) << 1);
    int h    = kk & 1;
    __half* base = g_W + ((size_t)b * 2 + fh) * WHALF;
    size_t elem = ((size_t)ft * 32 + lane) * 8 + reg * 2 + h;

    #pragma unroll
    for (int u = 0; u < 3; u++)
        #pragma unroll
        for (int v = 0; v < 3; v++) {
            float s = bac;
            #pragma unroll
            for (int i = 0; i < 3; i++)
                #pragma unroll
                for (int j = 0; j < 3; j++)
                    s += maxi_s[(u + i) * 5 + (v + j)] * wa[i * 3 + j];
            float att = 1.f / (1.f + __expf(-s));
            float val = (wgt1_s[u * 3 + v] * w2c + b2c) * att;
            int tap = u * 3 + v;
            int kt = (cg * 9 + tap) * 2 + (ci >> 4);
            base[(size_t)kt * 2048 + elem] = __float2half_rn(val);
        }
}

// ============================================================================
// helpers
// ============================================================================
__device__ __forceinline__ uint32_t smem_u32(const void* p) {
    uint32_t a;
    asm("{ .reg .u64 t; cvta.to.shared.u64 t, %1; cvt.u32.u64 %0, t; }" : "=r"(a) : "l"(p));
    return a;
}
__device__ __forceinline__ uint32_t pkh2(float lo, float hi) {
    __half2 h = __floats2half2_rn(lo, hi);
    return *(uint32_t*)&h;
}
__device__ __forceinline__ void mma16(float* d, const uint4 a,
                                      uint32_t b0, uint32_t b1) {
    asm volatile(
        "mma.sync.aligned.m16n8k16.row.col.f32.f16.f16.f32 "
        "{%0,%1,%2,%3}, {%4,%5,%6,%7}, {%8,%9}, {%0,%1,%2,%3};"
        : "+f"(d[0]), "+f"(d[1]), "+f"(d[2]), "+f"(d[3])
        : "r"(a.x), "r"(a.y), "r"(a.z), "r"(a.w), "r"(b0), "r"(b1));
}
__device__ __forceinline__ void cpasync16(uint32_t dst, const void* src) {
    asm volatile("cp.async.cg.shared.global [%0], [%1], 16;" :: "r"(dst), "l"(src));
}
#define CP_COMMIT() asm volatile("cp.async.commit_group;" ::: "memory")
#define CP_WAIT0()  asm volatile("cp.async.wait_group 0;" ::: "memory")

// ============================================================================
// Kernel 3: fp16 m16n8k16 mma.sync implicit GEMM, fragment-order A.
// CTA = (b, f_half 128 filters, 4 rows x 56 px). Warps 2(M) x 4(N).
// x window packed as fp16x2 channel pairs: xw32[cpair(16)][row(6)][col(58)],
// stride 360 u32 (conflict-free B loads). A stage = 3 taps = 24KB linear.
// ============================================================================
#define XWS     360                // uint32 stride per cpair
#define OFF_XR  23040              // xw32: 16*360*4 B
#define OFF_A   66048              // xraw: 32*84*16 = 43008 B
#define A_BUF   24576              // 6 kt * 2048 halves * 2 B
#define CONV_SMEM (OFF_A + 2 * A_BUF)   // 115200 B

__global__ void __launch_bounds__(256, 1)
conv_mma(const float* __restrict__ x, float* __restrict__ out)
{
    extern __shared__ char smem[];
    uint32_t* xw32 = (uint32_t*)smem;
    float* xraw = (float*)(smem + OFF_XR);
    const uint32_t sb = smem_u32(smem);
    const int tid = threadIdx.x, lid = tid & 31, wid = tid >> 5;
    const int g = lid >> 2, t4 = lid & 3;
    const int warpM = wid & 1, warpN = wid >> 1;    // 2 x 4
    const int b = blockIdx.z, fh = blockIdx.y, row0 = blockIdx.x * 4;

    const float* xb = x + (size_t)b * CH * HW;
    const __half* wb = g_W + ((size_t)b * 2 + fh) * WHALF;

    float d[4][7][4];
    #pragma unroll
    for (int i = 0; i < 4; i++)
        #pragma unroll
        for (int j = 0; j < 7; j++)
            #pragma unroll
            for (int k = 0; k < 4; k++) d[i][j][k] = 0.f;

    // ---- A stage: 24KB linear copy (stage = 3 taps = 6 k16-tiles) ----
    auto stageA = [&](int stageIdx, int buf) {
        const __half* src = wb + (size_t)stageIdx * 12288;
        uint32_t dbase = sb + OFF_A + (uint32_t)buf * A_BUF;
        #pragma unroll
        for (int i = 0; i < 6; ++i) {
            int idx = i * 256 + tid;           // 0..1535 chunks of 16B
            cpasync16(dbase + (uint32_t)idx * 16, src + idx * 8);
        }
        CP_COMMIT();
    };
    // ---- X prefetch: raw 32-ch fp32 window -> xraw ----
    auto stageX = [&](int cg) {
        for (int i = tid; i < 32 * 84; i += 256) {
            int c2 = i / 84, rem = i - c2 * 84;
            int rw = rem / 14, gq = rem - rw * 14;
            int grow = row0 - 1 + rw;
            if ((unsigned)grow < 56u)
                cpasync16(sb + OFF_XR + (uint32_t)i * 16,
                          xb + (size_t)(cg * 32 + c2) * HW + grow * 56 + 4 * gq);
        }
        CP_COMMIT();
    };

    // zero packed window once (halo stays zero)
    for (int i = tid; i < (16 * XWS) / 4; i += 256)
        ((uint4*)xw32)[i] = make_uint4(0, 0, 0, 0);
    stageX(0);
    stageA(0, 0);

    int stage = 0;
    for (int cg = 0; cg < 8; ++cg) {
        CP_WAIT0();
        __syncthreads();
        // ---- pack raw fp32 -> fp16x2 channel pairs ----
        for (int i = tid; i < 16 * 84; i += 256) {
            int cp = i / 84, rem = i - cp * 84;
            int rw = rem / 14, gq = rem - rw * 14;
            int grow = row0 - 1 + rw;
            if ((unsigned)grow < 56u) {
                float4 va = ((const float4*)xraw)[(2 * cp) * 84 + rem];
                float4 vb = ((const float4*)xraw)[(2 * cp + 1) * 84 + rem];
                uint32_t* dst = xw32 + cp * XWS + rw * 58 + 4 * gq + 1;
                dst[0] = pkh2(va.x, vb.x);
                dst[1] = pkh2(va.y, vb.y);
                dst[2] = pkh2(va.z, vb.z);
                dst[3] = pkh2(va.w, vb.w);
            }
        }
        __syncthreads();

        for (int s = 0; s < 3; ++s, ++stage) {
            const int buf = stage & 1;
            if (s > 0) {
                CP_WAIT0();
                __syncthreads();
            }
            if (s < 2) {
                stageA(stage + 1, buf ^ 1);
            } else {
                if (cg < 7) stageX(cg + 1);
                if (stage + 1 < 24) stageA(stage + 1, buf ^ 1);
            }

            const uint32_t* as = (const uint32_t*)(smem + OFF_A + buf * A_BUF);
            #pragma unroll
            for (int tapo = 0; tapo < 3; ++tapo) {
                const int tap = s * 3 + tapo;
                const int ti = tap / 3, tj = tap - ti * 3;
                #pragma unroll
                for (int ksh = 0; ksh < 2; ++ksh) {
                    // A fragments: one LDS.128 per m-frag
                    uint4 A[4];
                    const uint32_t* abase = as
                        + ((tapo * 2 + ksh) * 8 + warpM * 4) * 128 + lid * 4;
                    #pragma unroll
                    for (int mf = 0; mf < 4; ++mf)
                        A[mf] = *(const uint4*)(abase + mf * 128);
                    const uint32_t* bbase = xw32 + (ksh * 8 + t4) * XWS
                                          + (warpN + ti) * 58 + tj + g;
                    #pragma unroll
                    for (int nf = 0; nf < 7; ++nf) {
                        uint32_t b0 = bbase[nf * 8];
                        uint32_t b1 = bbase[4 * XWS + nf * 8];
                        #pragma unroll
                        for (int mf = 0; mf < 4; ++mf)
                            mma16(d[mf][nf], A[mf], b0, b1);
                    }
                }
            }
        }
    }

    // ---- epilogue ----
    #pragma unroll
    for (int mf = 0; mf < 4; ++mf) {
        int mrow = fh * 128 + (warpM * 4 + mf) * 16 + g;
        float* o0 = out + (size_t)(b * CH + mrow) * HW + (row0 + warpN) * 56;
        float* o8 = o0 + 8 * (size_t)HW;
        #pragma unroll
        for (int nf = 0; nf < 7; ++nf) {
            int pix = nf * 8 + 2 * t4;
            *(float2*)(o0 + pix) = make_float2(d[mf][nf][0], d[mf][nf][1]);
            *(float2*)(o8 + pix) = make_float2(d[mf][nf][2], d[mf][nf][3]);
        }
    }
}

// ============================================================================
// launch — inputs: x, w1, b1, w2, b2, w_att, b_att
// ============================================================================
extern "C" void kernel_launch(void* const* d_in, const int* in_sizes, int n_in,
                              void* d_out, int out_size)
{
    const float* x     = (const float*)d_in[0];
    const float* w1    = (const float*)d_in[1];
    const float* b1    = (const float*)d_in[2];
    const float* w2    = (const float*)d_in[3];
    const float* b2    = (const float*)d_in[4];
    const float* w_att = (const float*)d_in[5];
    const float* b_att = (const float*)d_in[6];
    float* out = (float*)d_out;

    cudaFuncSetAttribute(conv_mma, cudaFuncAttributeMaxDynamicSharedMemorySize,
                         CONV_SMEM);

    pool_kernel<<<BATCH * CH, 256>>>(x, w1, b1);
    dim3 ggrid(CH, BATCH);
    gen_kernel<<<ggrid, 256>>>(w2, b2, w_att, b_att);
    dim3 cgrid(14, 2, BATCH);
    conv_mma<<<cgrid, 256, CONV_SMEM>>>(x, out);
}